// round 17
// baseline (speedup 1.0000x reference)
#include <cuda_runtime.h>
#include <cuda_fp16.h>
#include <math.h>
#include <stdint.h>

constexpr int Tn = 2048, Dn = 1024, Hn = 16, KVn = 8, HDn = 128, FFn = 3072, Ln = 5;
constexpr float EPSf = 1e-6f;

// ---------------- scratch ----------------
__device__ float g_h [Tn * Dn];
__device__ float g_cos[Tn * 64];
__device__ float g_sin[Tn * 64];

__device__ __align__(16) __half g_xh  [Tn * Dn];
__device__ __align__(16) __half g_aoh [Tn * Hn * HDn];
__device__ __align__(16) __half g_gh  [Tn * FFn];
__device__ __align__(16) __half g_q16 [Tn * Hn * HDn];
__device__ __align__(16) __half g_k16 [KVn * Tn * HDn];
__device__ __align__(16) __half g_vt16[KVn * HDn * Tn];

constexpr size_t W_Q  = 0;
constexpr size_t W_K  = W_Q + (size_t)Ln * Hn * HDn * Dn;
constexpr size_t W_V  = W_K + (size_t)Ln * KVn * HDn * Dn;
constexpr size_t W_O  = W_V + (size_t)Ln * KVn * HDn * Dn;
constexpr size_t W_G  = W_O + (size_t)Ln * Dn * Hn * HDn;
constexpr size_t W_U  = W_G + (size_t)Ln * FFn * Dn;
constexpr size_t W_D  = W_U + (size_t)Ln * FFn * Dn;
constexpr size_t W_TOT= W_D + (size_t)Ln * Dn * FFn;
__device__ __align__(16) __half g_w[W_TOT];

// ---------------- PTX helpers ----------------
__device__ __forceinline__ uint32_t sptr(const void* p) {
    return (uint32_t)__cvta_generic_to_shared(p);
}
__device__ __forceinline__ void ldm_x4(uint32_t* r, uint32_t addr) {
    asm volatile("ldmatrix.sync.aligned.m8n8.x4.shared.b16 {%0,%1,%2,%3}, [%4];"
                 : "=r"(r[0]), "=r"(r[1]), "=r"(r[2]), "=r"(r[3]) : "r"(addr));
}
__device__ __forceinline__ void mma_f16(float* c, const uint32_t* a, uint32_t b0, uint32_t b1) {
    asm volatile("mma.sync.aligned.m16n8k16.row.col.f32.f16.f16.f32 "
                 "{%0,%1,%2,%3}, {%4,%5,%6,%7}, {%8,%9}, {%0,%1,%2,%3};"
                 : "+f"(c[0]), "+f"(c[1]), "+f"(c[2]), "+f"(c[3])
                 : "r"(a[0]), "r"(a[1]), "r"(a[2]), "r"(a[3]), "r"(b0), "r"(b1));
}
__device__ __forceinline__ void cp_async16(uint32_t dst, const void* src) {
    asm volatile("cp.async.ca.shared.global [%0], [%1], 16;" :: "r"(dst), "l"(src));
}
__device__ __forceinline__ void cp_commit() {
    asm volatile("cp.async.commit_group;" ::: "memory");
}
template <int N>
__device__ __forceinline__ void cp_wait() {
    asm volatile("cp.async.wait_group %0;" :: "n"(N) : "memory");
}
__device__ __forceinline__ uint32_t h2u(__half2 h) { return *(uint32_t*)&h; }

// ---------------- weight fp16 conversion ----------------
struct Cv7 {
    const float4* s[7];
    __half* d[7];
    int cum[8];
};
__global__ void conv7_kernel(Cv7 a) {
    int idx = blockIdx.x * 256 + threadIdx.x;
    if (idx >= a.cum[7]) return;
    int s = 0;
#pragma unroll
    for (int i = 0; i < 6; i++) s += (idx >= a.cum[i + 1]) ? 1 : 0;
    int off = idx - a.cum[s];
    float4 v = a.s[s][off];
    ((uint2*)a.d[s])[off] = make_uint2(h2u(__floats2half2_rn(v.x, v.y)),
                                       h2u(__floats2half2_rn(v.z, v.w)));
}

// ---------------- RoPE tables ----------------
__global__ void rope_tables_kernel() {
    int t = blockIdx.x, j = threadIdx.x;
    float inv = 1.0f / powf(1.0e6f, (float)j * (1.0f / 64.0f));
    g_cos[t * 64 + j] = cosf((float)t * inv);
    g_sin[t * 64 + j] = sinf((float)t * inv);
}

// ---------------- RMSNorm rows ----------------
template <int HALF>
__global__ void rms_rows_kernel(const float* __restrict__ in,
                                const float* __restrict__ w,
                                float* __restrict__ out,
                                __half* __restrict__ oh) {
    int t = blockIdx.x;
    const float4* ip = (const float4*)(in + (size_t)t * Dn);
    const float4* wp = (const float4*)w;
    float4 v = ip[threadIdx.x];
    float s = v.x * v.x + v.y * v.y + v.z * v.z + v.w * v.w;
#pragma unroll
    for (int off = 16; off; off >>= 1) s += __shfl_xor_sync(0xffffffffu, s, off);
    __shared__ float ws[8];
    if ((threadIdx.x & 31) == 0) ws[threadIdx.x >> 5] = s;
    __syncthreads();
    float tot = 0.f;
#pragma unroll
    for (int i = 0; i < 8; i++) tot += ws[i];
    float r = rsqrtf(tot * (1.0f / (float)Dn) + EPSf);
    float4 wv = wp[threadIdx.x];
    float4 o = make_float4(v.x * r * wv.x, v.y * r * wv.y, v.z * r * wv.z, v.w * r * wv.w);
    if (HALF) {
        ((uint2*)(oh + (size_t)t * Dn))[threadIdx.x] =
            make_uint2(h2u(__floats2half2_rn(o.x, o.y)),
                       h2u(__floats2half2_rn(o.z, o.w)));
    } else {
        ((float4*)(out + (size_t)t * Dn))[threadIdx.x] = o;
    }
}

// ---------------- fp16 tensor-core GEMM NT (2-stage) with fused epilogues ----------------
// EPI: 0 = fp32 +=ADD, 2 = V (fp32 vals + fp16 V^T), 3 = Q norm+rope, 4 = K norm+rope
constexpr int HROWB = 144;
constexpr int ASTB  = 128 * HROWB;
#define HG_SMEM(BN) (2 * (128 + (BN)) * HROWB)

template <int ADD, int BN, int EPI>
__device__ __forceinline__ void hgemm_body(const __half* __restrict__ A,
                                           const __half* __restrict__ B,
                                           float* __restrict__ C,
                                           __half* __restrict__ Ch,
                                           const float* __restrict__ wnorm,
                                           int N, int K, int m0, int n0,
                                           char* smem) {
    constexpr int BSTB = BN * HROWB;
    constexpr int NT2  = BN / 32;
    const int tid = threadIdx.x, lane = tid & 31, wid = tid >> 5;
    const int wm = wid & 3, wn = wid >> 2;

    const __half* Ag = A + (size_t)m0 * K;
    const __half* Bg = B + (size_t)n0 * K;
    const uint32_t sA = sptr(smem);
    const uint32_t sB = sA + 2 * ASTB;

    float acc[2][BN / 16][4];
#pragma unroll
    for (int i = 0; i < 2; i++)
#pragma unroll
        for (int j = 0; j < BN / 16; j++)
#pragma unroll
            for (int q = 0; q < 4; q++) acc[i][j][q] = 0.f;

    const int frow = ((lane >> 3) & 1) * 8 + (lane & 7);
    const int fcol = (lane >> 4) * 16;
    const int nk = K >> 6;

    auto stage = [&](int st, int kt) {
        const __half* Ak = Ag + (size_t)kt * 64;
        const __half* Bk = Bg + (size_t)kt * 64;
        uint32_t da = sA + st * ASTB;
        uint32_t db = sB + st * BSTB;
#pragma unroll
        for (int it = 0; it < 4; ++it) {
            int ch = tid + it * 256;
            int row = ch >> 3, c16 = ch & 7;
            cp_async16(da + row * HROWB + c16 * 16, Ak + (size_t)row * K + c16 * 8);
        }
#pragma unroll
        for (int it = 0; it < BN / 32; ++it) {
            int ch = tid + it * 256;
            int row = ch >> 3, c16 = ch & 7;
            cp_async16(db + row * HROWB + c16 * 16, Bk + (size_t)row * K + c16 * 8);
        }
        cp_commit();
    };

    stage(0, 0);

    for (int i = 0; i < nk; ++i) {
        cp_wait<0>();
        __syncthreads();
        if (i + 1 < nk) stage((i + 1) & 1, i + 1);

        const int cur = i & 1;
        const uint32_t aaddr = sA + cur * ASTB + (wm * 32 + frow) * HROWB + fcol;
        const uint32_t baddr = sB + cur * BSTB + (wn * (BN / 2) + frow) * HROWB + fcol;
#pragma unroll
        for (int ks = 0; ks < 4; ++ks) {
            uint32_t af[2][4];
            ldm_x4(af[0], aaddr + ks * 32);
            ldm_x4(af[1], aaddr + 16 * HROWB + ks * 32);
#pragma unroll
            for (int n2 = 0; n2 < NT2; ++n2) {
                uint32_t bf[4];
                ldm_x4(bf, baddr + n2 * 16 * HROWB + ks * 32);
#pragma unroll
                for (int mt = 0; mt < 2; ++mt) {
                    mma_f16(acc[mt][n2 * 2],     af[mt], bf[0], bf[2]);
                    mma_f16(acc[mt][n2 * 2 + 1], af[mt], bf[1], bf[3]);
                }
            }
        }
    }

    const int row0 = m0 + wm * 32 + (lane >> 2);
    const int col0 = n0 + wn * (BN / 2) + (lane & 3) * 2;

    if (EPI == 3 || EPI == 4) {
        // ---- fused per-head RMSNorm + RoPE (BN == 128; one head per CTA) ----
        __syncthreads();
        float* sE = (float*)smem;     // [128][132] fp32
        const int lr = wm * 32 + (lane >> 2);
        const int lc = wn * 64 + (lane & 3) * 2;
#pragma unroll
        for (int mt = 0; mt < 2; ++mt)
#pragma unroll
            for (int nt = 0; nt < BN / 16; ++nt) {
                int r = lr + mt * 16, c = lc + nt * 8;
                *(float2*)&sE[r * 132 + c] = make_float2(acc[mt][nt][0], acc[mt][nt][1]);
                *(float2*)&sE[(r + 8) * 132 + c] = make_float2(acc[mt][nt][2], acc[mt][nt][3]);
            }
        __syncthreads();

        const int head = n0 >> 7;
        const int d0 = lane * 4;
        const int dd = (d0 < 64) ? d0 + 64 : d0 - 64;
        const float sgn = (d0 < 64) ? -1.f : 1.f;
        const float w0 = wnorm[d0], w1 = wnorm[d0 + 1], w2 = wnorm[d0 + 2], w3 = wnorm[d0 + 3];
        const float wo0 = wnorm[dd], wo1 = wnorm[dd + 1], wo2 = wnorm[dd + 2], wo3 = wnorm[dd + 3];
        const int j0 = d0 & 63;

        for (int it = 0; it < 16; ++it) {
            int row = wid * 16 + it;
            int t = m0 + row;
            float4 v  = *(float4*)&sE[row * 132 + d0];
            float4 vo = *(float4*)&sE[row * 132 + dd];
            float ss = v.x * v.x + v.y * v.y + v.z * v.z + v.w * v.w;
#pragma unroll
            for (int o = 16; o; o >>= 1) ss += __shfl_xor_sync(0xffffffffu, ss, o);
            float rr = rsqrtf(ss * (1.0f / 128.f) + EPSf);
            float c0 = g_cos[t * 64 + j0],     s0 = g_sin[t * 64 + j0];
            float c1 = g_cos[t * 64 + j0 + 1], s1 = g_sin[t * 64 + j0 + 1];
            float c2 = g_cos[t * 64 + j0 + 2], s2 = g_sin[t * 64 + j0 + 2];
            float c3 = g_cos[t * 64 + j0 + 3], s3 = g_sin[t * 64 + j0 + 3];
            float o0 = v.x * rr * w0 * c0 + sgn * vo.x * rr * wo0 * s0;
            float o1 = v.y * rr * w1 * c1 + sgn * vo.y * rr * wo1 * s1;
            float o2 = v.z * rr * w2 * c2 + sgn * vo.z * rr * wo2 * s2;
            float o3 = v.w * rr * w3 * c3 + sgn * vo.w * rr * wo3 * s3;
            if (EPI == 3) {
                constexpr float sc = 0.0883883476483184f;
                uint2 p = make_uint2(h2u(__floats2half2_rn(o0 * sc, o1 * sc)),
                                     h2u(__floats2half2_rn(o2 * sc, o3 * sc)));
                *(uint2*)&Ch[((size_t)t * Hn + head) * HDn + d0] = p;
            } else {
                size_t idx = ((size_t)head * Tn + t) * HDn + d0;
                *(float4*)&C[idx] = make_float4(o0, o1, o2, o3);
                *(uint2*)&Ch[idx] = make_uint2(h2u(__floats2half2_rn(o0, o1)),
                                               h2u(__floats2half2_rn(o2, o3)));
            }
        }
        return;
    }

#pragma unroll
    for (int mt = 0; mt < 2; ++mt)
#pragma unroll
        for (int nt = 0; nt < BN / 16; ++nt) {
            int r = row0 + mt * 16;
            int c = col0 + nt * 8;
            float2 v0 = make_float2(acc[mt][nt][0], acc[mt][nt][1]);
            float2 v1 = make_float2(acc[mt][nt][2], acc[mt][nt][3]);
            if (EPI == 2) {
                *(float2*)&C[((size_t)(c >> 7) * Tn + r) * HDn + (c & 127)] = v0;
                *(float2*)&C[((size_t)(c >> 7) * Tn + (r + 8)) * HDn + (c & 127)] = v1;
                size_t vb = ((size_t)(c >> 7) * HDn + (c & 127)) * Tn;
                Ch[vb + r]          = __float2half(v0.x);
                Ch[vb + Tn + r]     = __float2half(v0.y);
                Ch[vb + r + 8]      = __float2half(v1.x);
                Ch[vb + Tn + r + 8] = __float2half(v1.y);
            } else {
                float2* p0 = (float2*)&C[(size_t)r * N + c];
                float2* p1 = (float2*)&C[(size_t)(r + 8) * N + c];
                if (ADD) {
                    float2 o0 = *p0, o1 = *p1;
                    v0.x += o0.x; v0.y += o0.y; v1.x += o1.x; v1.y += o1.y;
                }
                *p0 = v0;
                *p1 = v1;
            }
        }
}

// fused QKV + norm/rope: grid.x = 16 (q) + 8 (k) + 8 (v)
__global__ __launch_bounds__(256, 2) void hg_qkv_kernel(
    const __half* __restrict__ xh,
    const __half* __restrict__ wq, const __half* __restrict__ wk, const __half* __restrict__ wv,
    const float* __restrict__ qn, const float* __restrict__ kn,
    __half* __restrict__ q16, float* __restrict__ klayer, __half* __restrict__ k16,
    float* __restrict__ vlayer, __half* __restrict__ vt16) {
    extern __shared__ char smem[];
    int bx = blockIdx.x, m0 = blockIdx.y * 128;
    if (bx < 16)
        hgemm_body<0, 128, 3>(xh, wq, nullptr, q16, qn, Hn * HDn, Dn, m0, bx * 128, smem);
    else if (bx < 24)
        hgemm_body<0, 128, 4>(xh, wk, klayer, k16, kn, KVn * HDn, Dn, m0, (bx - 16) * 128, smem);
    else
        hgemm_body<0, 128, 2>(xh, wv, vlayer, vt16, nullptr, KVn * HDn, Dn, m0, (bx - 24) * 128, smem);
}

// gate+up in one CTA with fused silu(g)*u epilogue; grid (FFn/64, Tn/128)
__global__ __launch_bounds__(256, 2) void hg_gusilu_kernel(
    const __half* __restrict__ xh,
    const __half* __restrict__ wg, const __half* __restrict__ wu,
    __half* __restrict__ out) {
    extern __shared__ char smem[];
    const int m0 = blockIdx.y * 128, n0 = blockIdx.x * 64;
    const int tid = threadIdx.x, lane = tid & 31, wid = tid >> 5;
    const int wm = wid & 3, wn = wid >> 2;

    const __half* Ag = xh + (size_t)m0 * Dn;
    const __half* Gg = wg + (size_t)n0 * Dn;
    const __half* Ug = wu + (size_t)n0 * Dn;
    const uint32_t sA = sptr(smem);
    const uint32_t sB = sA + 2 * ASTB;
    constexpr int BSTB = 128 * HROWB;

    float ag[2][4][4], au[2][4][4];
#pragma unroll
    for (int i = 0; i < 2; i++)
#pragma unroll
        for (int j = 0; j < 4; j++)
#pragma unroll
            for (int q = 0; q < 4; q++) { ag[i][j][q] = 0.f; au[i][j][q] = 0.f; }

    const int frow = ((lane >> 3) & 1) * 8 + (lane & 7);
    const int fcol = (lane >> 4) * 16;
    const int nk = Dn >> 6;

    auto stage = [&](int st, int kt) {
        const __half* Ak = Ag + (size_t)kt * 64;
        const __half* Gk = Gg + (size_t)kt * 64;
        const __half* Uk = Ug + (size_t)kt * 64;
        uint32_t da = sA + st * ASTB;
        uint32_t db = sB + st * BSTB;
#pragma unroll
        for (int it = 0; it < 4; ++it) {
            int ch = tid + it * 256;
            int row = ch >> 3, c16 = ch & 7;
            cp_async16(da + row * HROWB + c16 * 16, Ak + (size_t)row * Dn + c16 * 8);
        }
#pragma unroll
        for (int it = 0; it < 2; ++it) {
            int ch = tid + it * 256;
            int row = ch >> 3, c16 = ch & 7;
            cp_async16(db + row * HROWB + c16 * 16, Gk + (size_t)row * Dn + c16 * 8);
            cp_async16(db + (64 + row) * HROWB + c16 * 16, Uk + (size_t)row * Dn + c16 * 8);
        }
        cp_commit();
    };

    stage(0, 0);

    for (int i = 0; i < nk; ++i) {
        cp_wait<0>();
        __syncthreads();
        if (i + 1 < nk) stage((i + 1) & 1, i + 1);

        const int cur = i & 1;
        const uint32_t aaddr = sA + cur * ASTB + (wm * 32 + frow) * HROWB + fcol;
        const uint32_t gaddr = sB + cur * BSTB + (wn * 32 + frow) * HROWB + fcol;
        const uint32_t uaddr = gaddr + 64 * HROWB;
#pragma unroll
        for (int ks = 0; ks < 4; ++ks) {
            uint32_t af[2][4];
            ldm_x4(af[0], aaddr + ks * 32);
            ldm_x4(af[1], aaddr + 16 * HROWB + ks * 32);
#pragma unroll
            for (int n2 = 0; n2 < 2; ++n2) {
                uint32_t bg[4], bu[4];
                ldm_x4(bg, gaddr + n2 * 16 * HROWB + ks * 32);
                ldm_x4(bu, uaddr + n2 * 16 * HROWB + ks * 32);
#pragma unroll
                for (int mt = 0; mt < 2; ++mt) {
                    mma_f16(ag[mt][n2 * 2],     af[mt], bg[0], bg[2]);
                    mma_f16(ag[mt][n2 * 2 + 1], af[mt], bg[1], bg[3]);
                    mma_f16(au[mt][n2 * 2],     af[mt], bu[0], bu[2]);
                    mma_f16(au[mt][n2 * 2 + 1], af[mt], bu[1], bu[3]);
                }
            }
        }
    }

    const int row0 = m0 + wm * 32 + (lane >> 2);
    const int col0 = n0 + wn * 32 + (lane & 3) * 2;
#pragma unroll
    for (int mt = 0; mt < 2; ++mt)
#pragma unroll
        for (int nt = 0; nt < 4; ++nt) {
            int r = row0 + mt * 16;
            int c = col0 + nt * 8;
            float g0 = ag[mt][nt][0], g1 = ag[mt][nt][1];
            float g2 = ag[mt][nt][2], g3 = ag[mt][nt][3];
            float r0 = g0 / (1.0f + __expf(-g0)) * au[mt][nt][0];
            float r1 = g1 / (1.0f + __expf(-g1)) * au[mt][nt][1];
            float r2 = g2 / (1.0f + __expf(-g2)) * au[mt][nt][2];
            float r3 = g3 / (1.0f + __expf(-g3)) * au[mt][nt][3];
            *(__half2*)&out[(size_t)r * FFn + c]       = __floats2half2_rn(r0, r1);
            *(__half2*)&out[(size_t)(r + 8) * FFn + c] = __floats2half2_rn(r2, r3);
        }
}

__global__ __launch_bounds__(256, 2) void hg_add_kernel(
    const __half* __restrict__ a, const __half* __restrict__ b,
    float* __restrict__ C, int N, int K) {
    extern __shared__ char smem[];
    hgemm_body<1, 64, 0>(a, b, C, nullptr, nullptr, N, K, blockIdx.y * 128, blockIdx.x * 64, smem);
}

// ---------------- fp16 flash attention: 64 q-rows, 4 warps, 4 CTAs/SM ----------------
// grid (Hn, Tn/64): heads scan fastest, heavy q-tiles first. Single-buffered K/V;
// latency hidden by 4 resident CTAs. P aliases the K tile region after the S-loop.
constexpr int SKH = 136, SVH = 72, SPH = 72;   // strides in halves; x2 bytes must be 16B-aligned
constexpr int AQTB = 64 * SKH * 2;       // 17408 Q staging
constexpr int AKTB = 64 * SKH * 2;       // 17408 K tile (P aliases: 64*72*2 = 9216)
constexpr int AVTB = 128 * SVH * 2;      // 18432 V tile
constexpr int ATTN_SMEM = AQTB + AKTB + AVTB;  // 53248

__global__ __launch_bounds__(128, 4) void attn_h_kernel(const __half* __restrict__ Q16,
                                                        const __half* __restrict__ K16,
                                                        const __half* __restrict__ VT16,
                                                        __half* __restrict__ AO) {
    extern __shared__ char smraw[];
    const uint32_t sQ = sptr(smraw);
    const uint32_t sK = sQ + AQTB;
    const uint32_t sV = sK + AKTB;

    const int h = blockIdx.x;
    const int qt0 = (gridDim.y - 1 - blockIdx.y) * 64;  // heavy q-tiles launch first
    const int kv = h >> 1;
    const int tid = threadIdx.x, lane = tid & 31, wid = tid >> 5;
    const int frow = ((lane >> 3) & 1) * 8 + (lane & 7);
    const int fcol = (lane >> 4) * 16;
    const int r0 = lane >> 2, c0 = (lane & 3) * 2;
    const int nkt = (qt0 >> 6) + 1;

    const char* kbase = (const char*)(K16 + (size_t)kv * Tn * HDn);
    const char* vbase = (const char*)(VT16 + (size_t)kv * HDn * Tn);

    auto stageKV = [&](int kt) {
        const int kt0 = kt << 6;
        const char* ks = kbase + (size_t)kt0 * (HDn * 2);
#pragma unroll
        for (int it = 0; it < 8; ++it) {
            int ch = tid + it * 128;
            int row = ch >> 4, c = ch & 15;
            cp_async16(sK + row * (SKH * 2) + c * 16, ks + (size_t)row * 256 + c * 16);
        }
        const char* vs = vbase + (size_t)kt0 * 2;
#pragma unroll
        for (int it = 0; it < 8; ++it) {
            int ch = tid + it * 128;
            int row = ch >> 3, c = ch & 7;
            cp_async16(sV + row * (SVH * 2) + c * 16, vs + (size_t)row * (Tn * 2) + c * 16);
        }
        cp_commit();
    };

    // stage Q (64 rows)
    {
        const char* qs = (const char*)(Q16 + ((size_t)qt0 * Hn + h) * HDn);
#pragma unroll
        for (int it = 0; it < 8; ++it) {
            int ch = tid + it * 128;
            int row = ch >> 4, c = ch & 15;
            cp_async16(sQ + row * (SKH * 2) + c * 16,
                       qs + (size_t)row * (Hn * HDn * 2) + c * 16);
        }
        cp_commit();
    }

    float o[16][4];
#pragma unroll
    for (int i = 0; i < 16; i++)
#pragma unroll
        for (int j = 0; j < 4; j++) o[i][j] = 0.f;
    float mreg[2] = {-1e30f, -1e30f}, lreg[2] = {0.f, 0.f};

    const uint32_t qaddr = sQ + (wid * 16 + frow) * (SKH * 2) + fcol;
    const uint32_t kaddr = sK + frow * (SKH * 2) + fcol;
    const uint32_t vaddr = sV + frow * (SVH * 2) + fcol;
    const uint32_t myP = sK + wid * 16 * (SPH * 2);   // P aliases K tile region
    const uint32_t paddr = myP + frow * (SPH * 2) + fcol;

    for (int kt = 0; kt < nkt; ++kt) {
        const int kt0 = kt << 6;
        if (kt) __syncthreads();   // prior P/V reads done before restaging
        stageKV(kt);
        cp_wait<0>();
        __syncthreads();

        // ---- S = Q @ K^T (per warp: 16 rows x 64 cols); Q frags reloaded per ks ----
        float s[8][4];
#pragma unroll
        for (int i = 0; i < 8; i++)
#pragma unroll
            for (int j = 0; j < 4; j++) s[i][j] = 0.f;
#pragma unroll
        for (int ks = 0; ks < 8; ++ks) {
            uint32_t qf[4];
            ldm_x4(qf, qaddr + ks * 32);
#pragma unroll
            for (int ntp = 0; ntp < 4; ++ntp) {
                uint32_t bf[4];
                ldm_x4(bf, kaddr + ntp * 16 * (SKH * 2) + ks * 32);
                mma_f16(s[ntp * 2],     qf, bf[0], bf[2]);
                mma_f16(s[ntp * 2 + 1], qf, bf[1], bf[3]);
            }
        }

        if (kt == nkt - 1) {
            int rowg = qt0 + wid * 16 + r0;
#pragma unroll
            for (int nt = 0; nt < 8; ++nt) {
                int colg = kt0 + nt * 8 + c0;
                if (colg > rowg)          s[nt][0] = -1e30f;
                if (colg + 1 > rowg)      s[nt][1] = -1e30f;
                if (colg > rowg + 8)      s[nt][2] = -1e30f;
                if (colg + 1 > rowg + 8)  s[nt][3] = -1e30f;
            }
        }

        // ---- online softmax ----
#pragma unroll
        for (int hf = 0; hf < 2; ++hf) {
            float rm = -1e30f;
#pragma unroll
            for (int nt = 0; nt < 8; ++nt)
                rm = fmaxf(rm, fmaxf(s[nt][2 * hf], s[nt][2 * hf + 1]));
            rm = fmaxf(rm, __shfl_xor_sync(0xffffffffu, rm, 1));
            rm = fmaxf(rm, __shfl_xor_sync(0xffffffffu, rm, 2));
            float mn = fmaxf(mreg[hf], rm);
            float corr = __expf(mreg[hf] - mn);
            mreg[hf] = mn;
            float su = 0.f;
#pragma unroll
            for (int nt = 0; nt < 8; ++nt) {
                float e0 = __expf(s[nt][2 * hf] - mn);
                float e1 = __expf(s[nt][2 * hf + 1] - mn);
                s[nt][2 * hf] = e0;
                s[nt][2 * hf + 1] = e1;
                su += e0 + e1;
            }
            su += __shfl_xor_sync(0xffffffffu, su, 1);
            su += __shfl_xor_sync(0xffffffffu, su, 2);
            lreg[hf] = lreg[hf] * corr + su;
#pragma unroll
            for (int nt = 0; nt < 16; ++nt) {
                o[nt][2 * hf] *= corr;
                o[nt][2 * hf + 1] *= corr;
            }
        }

        // ---- P overwrites K region: all warps' K reads must be done ----
        __syncthreads();
#pragma unroll
        for (int nt = 0; nt < 8; ++nt) {
            *(uint32_t*)((char*)smraw + (myP - sQ) + r0 * (SPH * 2) + (nt * 8 + c0) * 2) =
                h2u(__floats2half2_rn(s[nt][0], s[nt][1]));
            *(uint32_t*)((char*)smraw + (myP - sQ) + (r0 + 8) * (SPH * 2) + (nt * 8 + c0) * 2) =
                h2u(__floats2half2_rn(s[nt][2], s[nt][3]));
        }
        __syncwarp();

        // ---- O += P @ V ----
#pragma unroll
        for (int ks = 0; ks < 4; ++ks) {
            uint32_t pf[4];
            ldm_x4(pf, paddr + ks * 32);
#pragma unroll
            for (int np = 0; np < 8; ++np) {
                uint32_t bf[4];
                ldm_x4(bf, vaddr + np * 16 * (SVH * 2) + ks * 32);
                mma_f16(o[2 * np],     pf, bf[0], bf[2]);
                mma_f16(o[2 * np + 1], pf, bf[1], bf[3]);
            }
        }
    }

    float inv0 = 1.0f / lreg[0], inv1 = 1.0f / lreg[1];
    int rowg = qt0 + wid * 16 + r0;
#pragma unroll
    for (int nt = 0; nt < 16; ++nt) {
        size_t base = (size_t)h * HDn + nt * 8 + c0;
        *(__half2*)&AO[(size_t)rowg * (Hn * HDn) + base] =
            __floats2half2_rn(o[nt][0] * inv0, o[nt][1] * inv0);
        *(__half2*)&AO[(size_t)(rowg + 8) * (Hn * HDn) + base] =
            __floats2half2_rn(o[nt][2] * inv1, o[nt][3] * inv1);
    }
}

// ---------------- host orchestration ----------------
extern "C" void kernel_launch(void* const* d_in, const int* in_sizes, int n_in,
                              void* d_out, int out_size) {
    const float* emb = (const float*)d_in[0];
    const float* ln1 = (const float*)d_in[1];
    const float* qw  = (const float*)d_in[2];
    const float* kw  = (const float*)d_in[3];
    const float* vw  = (const float*)d_in[4];
    const float* qn  = (const float*)d_in[5];
    const float* kn  = (const float*)d_in[6];
    const float* ow  = (const float*)d_in[7];
    const float* ln2 = (const float*)d_in[8];
    const float* gw  = (const float*)d_in[9];
    const float* uw  = (const float*)d_in[10];
    const float* dw  = (const float*)d_in[11];
    const float* nw  = (const float*)d_in[12];

    float* out  = (float*)d_out;
    float* keys = out + (size_t)Tn * Dn;
    float* vals = keys + (size_t)Ln * KVn * Tn * HDn;

    float* ph;
    __half *pxh, *paoh, *pgh, *pw, *pq16, *pk16, *pvt16;
    cudaGetSymbolAddress((void**)&ph,    g_h);
    cudaGetSymbolAddress((void**)&pxh,   g_xh);
    cudaGetSymbolAddress((void**)&paoh,  g_aoh);
    cudaGetSymbolAddress((void**)&pgh,   g_gh);
    cudaGetSymbolAddress((void**)&pw,    g_w);
    cudaGetSymbolAddress((void**)&pq16,  g_q16);
    cudaGetSymbolAddress((void**)&pk16,  g_k16);
    cudaGetSymbolAddress((void**)&pvt16, g_vt16);

    cudaFuncSetAttribute(attn_h_kernel, cudaFuncAttributeMaxDynamicSharedMemorySize, ATTN_SMEM);
    cudaFuncSetAttribute(hg_qkv_kernel, cudaFuncAttributeMaxDynamicSharedMemorySize, HG_SMEM(128));
    cudaFuncSetAttribute(hg_gusilu_kernel, cudaFuncAttributeMaxDynamicSharedMemorySize, HG_SMEM(128));
    cudaFuncSetAttribute(hg_add_kernel, cudaFuncAttributeMaxDynamicSharedMemorySize, HG_SMEM(64));

    {
        Cv7 a;
        size_t offs[7] = { W_Q, W_K, W_V, W_O, W_G, W_U, W_D };
        const float* srcs[7] = { qw, kw, vw, ow, gw, uw, dw };
        size_t ns[7] = {
            (size_t)Ln * Hn * HDn * Dn, (size_t)Ln * KVn * HDn * Dn,
            (size_t)Ln * KVn * HDn * Dn, (size_t)Ln * Dn * Hn * HDn,
            (size_t)Ln * FFn * Dn, (size_t)Ln * FFn * Dn, (size_t)Ln * Dn * FFn };
        int cum = 0;
        for (int i = 0; i < 7; i++) {
            a.s[i] = (const float4*)srcs[i];
            a.d[i] = pw + offs[i];
            a.cum[i] = cum;
            cum += (int)(ns[i] / 4);
        }
        a.cum[7] = cum;
        conv7_kernel<<<(cum + 255) / 256, 256>>>(a);
    }

    cudaMemcpyAsync(ph, emb, sizeof(float) * Tn * Dn, cudaMemcpyDeviceToDevice);
    rope_tables_kernel<<<Tn, 64>>>();

    for (int i = 0; i < Ln; ++i) {
        float* klayer = keys + (size_t)i * KVn * Tn * HDn;
        float* vlayer = vals + (size_t)i * KVn * Tn * HDn;

        rms_rows_kernel<1><<<Tn, 256>>>(ph, ln1 + (size_t)i * Dn, nullptr, pxh);

        hg_qkv_kernel<<<dim3(32, Tn / 128), 256, HG_SMEM(128)>>>(
            pxh,
            pw + W_Q + (size_t)i * (Hn * HDn) * Dn,
            pw + W_K + (size_t)i * (KVn * HDn) * Dn,
            pw + W_V + (size_t)i * (KVn * HDn) * Dn,
            qn + (size_t)i * HDn, kn + (size_t)i * HDn,
            pq16, klayer, pk16, vlayer, pvt16);

        attn_h_kernel<<<dim3(Hn, Tn / 64), 128, ATTN_SMEM>>>(pq16, pk16, pvt16, paoh);

        hg_add_kernel<<<dim3(Dn / 64, Tn / 128), 256, HG_SMEM(64)>>>(
            paoh, pw + W_O + (size_t)i * Dn * (Hn * HDn), ph, Dn, Hn * HDn);

        rms_rows_kernel<1><<<Tn, 256>>>(ph, ln2 + (size_t)i * Dn, nullptr, pxh);

        hg_gusilu_kernel<<<dim3(FFn / 64, Tn / 128), 256, HG_SMEM(128)>>>(
            pxh,
            pw + W_G + (size_t)i * FFn * Dn,
            pw + W_U + (size_t)i * FFn * Dn,
            pgh);

        hg_add_kernel<<<dim3(Dn / 64, Tn / 128), 256, HG_SMEM(64)>>>(
            pgh, pw + W_D + (size_t)i * Dn * FFn, ph, Dn, FFn);
    }

    rms_rows_kernel<0><<<Tn, 256>>>(ph, nw, out, nullptr);
}